// round 2
// baseline (speedup 1.0000x reference)
#include <cuda_runtime.h>
#include <cstdint>

typedef unsigned long long ull;

// ---- constants ----
__constant__ float cA[5][5] = {
  {(float)(1.0/5.0), 0.f, 0.f, 0.f, 0.f},
  {(float)(3.0/40.0), (float)(9.0/40.0), 0.f, 0.f, 0.f},
  {(float)(44.0/45.0), (float)(-56.0/15.0), (float)(32.0/9.0), 0.f, 0.f},
  {(float)(19372.0/6561.0), (float)(-25360.0/2187.0), (float)(64448.0/6561.0), (float)(-212.0/729.0), 0.f},
  {(float)(9017.0/3168.0), (float)(-355.0/33.0), (float)(46732.0/5247.0), (float)(49.0/176.0), (float)(-5103.0/18656.0)},
};
__constant__ float cC[5]  = {0.2f, 0.3f, 0.8f, (float)(8.0/9.0), 1.0f};
__constant__ float cBW[6] = {(float)(35.0/384.0), 0.f, (float)(500.0/1113.0),
                             (float)(125.0/192.0), (float)(-2187.0/6784.0), (float)(11.0/84.0)};

// ---- smem layout (float offsets) ----
#define oM   0
#define oB1  128
#define oU1  256
#define oB2  384
#define oXs  512     /* 512: pair-interleaved stage x */
#define oA   1024    /* 512: pair-interleaved tanh */
#define oHP  1536    /* 1024: 2 k-half partials */
#define oPb  2560    /* 1024: double-buffered exchange */
#define oTrb 3584    /* 8 */
#define oKs  3592    /* 6*512 */
#define oY   6664    /* 512 */
#define oKld 7176    /* 24 */
#define oKkl 7200    /* 24 */
#define oScr 7224    /* 16 */
#define oLd  7240
#define oKl  7244
#define oLp  7248
#define SMF  7252

__device__ __forceinline__ ull pk(float w) {
  ull r; asm("mov.b64 %0, {%1, %2};" : "=l"(r) : "f"(w), "f"(w)); return r;
}
__device__ __forceinline__ ull mk2(float a, float b) {
  ull r; asm("mov.b64 %0, {%1, %2};" : "=l"(r) : "f"(a), "f"(b)); return r;
}
__device__ __forceinline__ float lo32(ull v) { return __uint_as_float((unsigned)v); }
__device__ __forceinline__ float hi32(ull v) { return __uint_as_float((unsigned)(v >> 32)); }
__device__ __forceinline__ ull f2fma(ull a, ull b, ull c) {
  ull d; asm("fma.rn.f32x2 %0,%1,%2,%3;" : "=l"(d) : "l"(a), "l"(b), "l"(c)); return d;
}
__device__ __forceinline__ ull f2add(ull a, ull b) {
  ull d; asm("add.rn.f32x2 %0,%1,%2;" : "=l"(d) : "l"(a), "l"(b)); return d;
}
__device__ __forceinline__ ull f2mul(ull a, ull b) {
  ull d; asm("mul.rn.f32x2 %0,%1,%2;" : "=l"(d) : "l"(a), "l"(b)); return d;
}
__device__ __forceinline__ float wsum(float v) {
#pragma unroll
  for (int o = 16; o > 0; o >>= 1) v += __shfl_xor_sync(0xffffffffu, v, o);
  return v;
}
__device__ __forceinline__ uint32_t smem_u32(const void* p) {
  uint32_t a;
  asm("{.reg .u64 t; cvta.to.shared.u64 t, %1; cvt.u32.u64 %0, t;}" : "=r"(a) : "l"(p));
  return a;
}
__device__ __forceinline__ ull ldc64(uint32_t addr, uint32_t rank) {
  uint32_t ra; asm("mapa.shared::cluster.u32 %0, %1, %2;" : "=r"(ra) : "r"(addr), "r"(rank));
  ull v; asm volatile("ld.shared::cluster.b64 %0, [%1];" : "=l"(v) : "r"(ra)); return v;
}
__device__ __forceinline__ float ldcf(uint32_t addr, uint32_t rank) {
  uint32_t ra; asm("mapa.shared::cluster.u32 %0, %1, %2;" : "=r"(ra) : "r"(addr), "r"(rank));
  float v; asm volatile("ld.shared::cluster.f32 %0, [%1];" : "=f"(v) : "r"(ra)); return v;
}
__device__ __forceinline__ void csync() {
  asm volatile("barrier.cluster.arrive.aligned;" ::: "memory");
  asm volatile("barrier.cluster.wait.aligned;" ::: "memory");
}

// GEMM over this thread's k-half: accumulates pair-interleaved partials.
#define GEMM_HALF(WREG, SRCOFF, DSTOFF) do {                                   \
  ull accA = 0ull, accB = 0ull;                                                \
  const int kb2 = kh << 6;                                                     \
  _Pragma("unroll")                                                            \
  for (int i = 0; i < 64; i += 2) {                                            \
    ulonglong2 xa = *(const ulonglong2*)&sm[(SRCOFF) + ((kb2 + i) << 1)];      \
    ulonglong2 xb = *(const ulonglong2*)&sm[(SRCOFF) + 256 + ((kb2 + i) << 1)];\
    ull w0 = pk(WREG[i]), w1 = pk(WREG[i + 1]);                                \
    accA = f2fma(w0, xa.x, accA); accB = f2fma(w0, xb.x, accB);                \
    accA = f2fma(w1, xa.y, accA); accB = f2fma(w1, xb.y, accB);                \
  }                                                                            \
  *(ull*)&sm[(DSTOFF) + (kh << 9) + (c << 1)]       = accA;                    \
  *(ull*)&sm[(DSTOFF) + (kh << 9) + 256 + (c << 1)] = accB;                    \
} while (0)

__global__ void __launch_bounds__(256, 1) __cluster_dims__(4, 1, 1)
vino_kernel(const float* __restrict__ x0g, const float* __restrict__ W1g,
            const float* __restrict__ b1g, const float* __restrict__ u1g,
            const float* __restrict__ W2g, const float* __restrict__ b2g,
            const int* __restrict__ nsp, float* __restrict__ out, int B) {
  __shared__ float sm[SMF];
  const int t = threadIdx.x;
  const int w = t >> 5, lane = t & 31;
  const int c = t & 127, kh = t >> 7;
  uint32_t rank; asm("mov.u32 %0, %%cluster_ctarank;" : "=r"(rank));
  const int hbase = (int)rank << 7;
  const int sb = (blockIdx.x >> 2) << 2;

  // ---- persistent weight registers ----
  float w1r[64], w2r[64];
#pragma unroll
  for (int i = 0; i < 64; ++i) w1r[i] = W1g[((kh << 6) + i) * 512 + hbase + c];
#pragma unroll
  for (int i = 0; i < 64; ++i) w2r[i] = W2g[(hbase + (kh << 6) + i) * 128 + c];

  // ---- consts + trace diagonal M ----
  if (t < 128) {
    sm[oB1 + t] = b1g[hbase + t];
    sm[oU1 + t] = u1g[hbase + t];
    sm[oB2 + t] = b2g[t];
    float m = 0.f;
#pragma unroll 4
    for (int i = 0; i < 128; ++i)
      m = fmaf(W1g[i * 512 + hbase + t], W2g[(hbase + t) * 128 + i], m);
    sm[oM + t] = m;
  }
  // ---- state init (pair-interleaved: idx = g*256 + d*2 + sp, s = 2g+sp) ----
  {
    const int d = t & 127, g = t >> 7, ib = (g << 8) + (d << 1);
    sm[oY + ib]     = x0g[(sb + 2 * g) * 128 + d];
    sm[oY + ib + 1] = x0g[(sb + 2 * g + 1) * 128 + d];
  }
  if (t < 4) { sm[oLd + t] = 0.f; sm[oKl + t] = 0.f; }
  __syncthreads();

  // ---- log p(x0) ----
  {
    const int d = t & 127, g = t >> 7, ib = (g << 8) + (d << 1);
    float q0 = sm[oY + ib], q1 = sm[oY + ib + 1];
    float s0 = wsum(q0 * q0), s1 = wsum(q1 * q1);
    if (lane == 0) { sm[oScr + w * 2] = s0; sm[oScr + w * 2 + 1] = s1; }
  }
  __syncthreads();
  if (t < 4) {
    const int g = t >> 1, sp = t & 1;
    float ss = 0.f;
#pragma unroll
    for (int q = 0; q < 4; ++q) ss += sm[oScr + ((g * 4 + q) << 1) + sp];
    sm[oLp + t] = -0.5f * ss - 117.6241322501981f;  // 64*log(2*pi)
  }
  __syncthreads();

  const int ns = *nsp;
  const float dt = 1.0f / (float)ns;
  const uint32_t sbase = smem_u32(sm);
  int p = 0;

  for (int step = 0; step < ns; ++step) {
    const float tstep = (float)step * dt;
#pragma unroll 1
    for (int stage = 0; stage < 6; ++stage) {
      // stage state
      if (stage == 0) {
        sm[oXs + t] = sm[oY + t];
        sm[oXs + 256 + t] = sm[oY + 256 + t];
      } else {
#pragma unroll 2
        for (int half = 0; half < 2; ++half) {
          const int e = t + (half << 8);
          float acc = 0.f;
          for (int j = 0; j < stage; ++j)
            acc = fmaf(cA[stage - 1][j], sm[oKs + (j << 9) + e], acc);
          sm[oXs + e] = sm[oY + e] + dt * acc;
        }
      }
      const float tcur = tstep + ((stage == 0) ? 0.f : cC[stage - 1]) * dt;
      __syncthreads();

      GEMM_HALF(w1r, oXs, oHP);
      __syncthreads();

      // tanh + trace partial
      {
        const int g = kh, ib = (g << 8) + (c << 1);
        ull h01 = f2add(*(const ull*)&sm[oHP + ib], *(const ull*)&sm[oHP + 512 + ib]);
        h01 = f2add(h01, pk(sm[oB1 + c] + tcur * sm[oU1 + c]));
        float a0 = tanhf(lo32(h01)), a1 = tanhf(hi32(h01));
        *(ull*)&sm[oA + ib] = mk2(a0, a1);
        float mc = sm[oM + c];
        float t0 = wsum((1.f - a0 * a0) * mc), t1 = wsum((1.f - a1 * a1) * mc);
        if (lane == 0) { sm[oScr + w * 2] = t0; sm[oScr + w * 2 + 1] = t1; }
      }
      __syncthreads();
      if (t < 4) {
        const int g = t >> 1, sp = t & 1;
        float tr = 0.f;
#pragma unroll
        for (int q = 0; q < 4; ++q) tr += sm[oScr + ((g * 4 + q) << 1) + sp];
        sm[oTrb + p * 4 + t] = tr;
      }

      GEMM_HALF(w2r, oA, oHP);
      __syncthreads();
      // fold k-halves into exchange buffer
      {
        const int e = t << 1;
        ull v = f2add(*(const ull*)&sm[oHP + e], *(const ull*)&sm[oHP + 512 + e]);
        *(ull*)&sm[oPb + (p << 9) + e] = v;
      }
      csync();

      // assemble dxdt from 4 ranks, trace, kl dot
      {
        const int d = t & 127, g = t >> 7, ib = (g << 8) + (d << 1);
        const uint32_t pa = sbase + (uint32_t)(oPb + (p << 9) + ib) * 4u;
        ull acc = ldc64(pa, 0);
        acc = f2add(acc, ldc64(pa, 1));
        acc = f2add(acc, ldc64(pa, 2));
        acc = f2add(acc, ldc64(pa, 3));
        acc = f2add(acc, pk(sm[oB2 + d]));
        *(ull*)&sm[oKs + (stage << 9) + ib] = acc;
        ull pr = f2mul(*(const ull*)&sm[oXs + ib], acc);
        float p0 = wsum(lo32(pr)), p1 = wsum(hi32(pr));
        if (lane == 0) { sm[oScr + w * 2] = p0; sm[oScr + w * 2 + 1] = p1; }
      }
      __syncthreads();
      if (t < 4) {
        const int g = t >> 1, sp = t & 1;
        float dot = 0.f;
#pragma unroll
        for (int q = 0; q < 4; ++q) dot += sm[oScr + ((g * 4 + q) << 1) + sp];
        float tr = 0.f;
        const uint32_t ta = sbase + (uint32_t)(oTrb + p * 4 + t) * 4u;
#pragma unroll
        for (uint32_t r = 0; r < 4; ++r) tr += ldcf(ta, r);
        sm[oKld + stage * 4 + t] = -tr;
        sm[oKkl + stage * 4 + t] = dot - tr;
      }
      __syncthreads();
      p ^= 1;
    }

    // step update with BW weights
#pragma unroll 2
    for (int half = 0; half < 2; ++half) {
      const int e = t + (half << 8);
      float acc = cBW[0] * sm[oKs + e];
#pragma unroll
      for (int j = 2; j < 6; ++j) acc = fmaf(cBW[j], sm[oKs + (j << 9) + e], acc);
      sm[oY + e] += dt * acc;
    }
    if (t < 4) {
      float ad = 0.f, ak = 0.f;
#pragma unroll
      for (int j = 0; j < 6; ++j) {
        ad = fmaf(cBW[j], sm[oKld + j * 4 + t], ad);
        ak = fmaf(cBW[j], sm[oKkl + j * 4 + t], ak);
      }
      sm[oLd + t] += dt * ad;
      sm[oKl + t] += dt * ak;
    }
    __syncthreads();
  }

  csync();  // keep SMEM alive until peers finish reading
  // outputs: z (B*128), then log_px (B), then kl (B)
  {
    const int d = t & 127, g = t >> 7, ib = (g << 8) + (d << 1);
    out[(sb + 2 * g) * 128 + d]     = sm[oY + ib];
    out[(sb + 2 * g + 1) * 128 + d] = sm[oY + ib + 1];
  }
  if (t < 4) {
    out[B * 128 + sb + t]     = sm[oLp + t] + sm[oLd + t];
    out[B * 128 + B + sb + t] = sm[oKl + t];
  }
}

extern "C" void kernel_launch(void* const* d_in, const int* in_sizes, int n_in,
                              void* d_out, int out_size) {
  const float* x0 = (const float*)d_in[0];
  const float* W1 = (const float*)d_in[1];
  const float* b1 = (const float*)d_in[2];
  const float* u1 = (const float*)d_in[3];
  const float* W2 = (const float*)d_in[4];
  const float* b2 = (const float*)d_in[5];
  const int*   ns = (const int*)d_in[6];
  float* out = (float*)d_out;
  int B = in_sizes[0] / 128;
  vino_kernel<<<B, 256>>>(x0, W1, b1, u1, W2, b2, ns, out, B);
}

// round 3
// speedup vs baseline: 1.4522x; 1.4522x over previous
#include <cuda_runtime.h>
#include <cstdint>

typedef unsigned long long ull;

// time offsets C and weights BW, indexed by stage 0..5
__constant__ float cCC[6]  = {0.f, 0.2f, 0.3f, 0.8f, (float)(8.0/9.0), 1.0f};
__constant__ float cBWv[6] = {(float)(35.0/384.0), 0.f, (float)(500.0/1113.0),
                              (float)(125.0/192.0), (float)(-2187.0/6784.0),
                              (float)(11.0/84.0)};

// ---- smem layout (float offsets) ----
#define oXs  0        /* 512: pair-interleaved stage x */
#define oA   512      /* 512: pair-interleaved tanh */
#define oHP  1024     /* 2048: 4 k-quarter GEMM partials */
#define oPb  3072     /* 4096: double-buffered exchange [p][rank][512] */
#define oScr 7168     /* 32 */
#define oTx  7200     /* 4 */
#define oLp  7204     /* 4 */
#define SMF  7208

__device__ __forceinline__ ull pk(float w) {
  ull r; asm("mov.b64 %0, {%1, %2};" : "=l"(r) : "f"(w), "f"(w)); return r;
}
__device__ __forceinline__ ull mk2(float a, float b) {
  ull r; asm("mov.b64 %0, {%1, %2};" : "=l"(r) : "f"(a), "f"(b)); return r;
}
__device__ __forceinline__ float lo32(ull v) { return __uint_as_float((unsigned)v); }
__device__ __forceinline__ float hi32(ull v) { return __uint_as_float((unsigned)(v >> 32)); }
__device__ __forceinline__ ull f2fma(ull a, ull b, ull c) {
  ull d; asm("fma.rn.f32x2 %0,%1,%2,%3;" : "=l"(d) : "l"(a), "l"(b), "l"(c)); return d;
}
__device__ __forceinline__ ull f2add(ull a, ull b) {
  ull d; asm("add.rn.f32x2 %0,%1,%2;" : "=l"(d) : "l"(a), "l"(b)); return d;
}
__device__ __forceinline__ ull f2mul(ull a, ull b) {
  ull d; asm("mul.rn.f32x2 %0,%1,%2;" : "=l"(d) : "l"(a), "l"(b)); return d;
}
__device__ __forceinline__ float wsum(float v) {
#pragma unroll
  for (int o = 16; o > 0; o >>= 1) v += __shfl_xor_sync(0xffffffffu, v, o);
  return v;
}
__device__ __forceinline__ uint32_t smem_u32(const void* p) {
  uint32_t a;
  asm("{.reg .u64 t; cvta.to.shared.u64 t, %1; cvt.u32.u64 %0, t;}" : "=r"(a) : "l"(p));
  return a;
}
__device__ __forceinline__ uint32_t mapa_u32(uint32_t addr, uint32_t rank) {
  uint32_t ra; asm("mapa.shared::cluster.u32 %0, %1, %2;" : "=r"(ra) : "r"(addr), "r"(rank));
  return ra;
}
__device__ __forceinline__ float ldcf(uint32_t addr, uint32_t rank) {
  uint32_t ra = mapa_u32(addr, rank);
  float v; asm volatile("ld.shared::cluster.f32 %0, [%1];" : "=f"(v) : "r"(ra)); return v;
}
__device__ __forceinline__ void csync() {
  asm volatile("barrier.cluster.arrive.aligned;" ::: "memory");
  asm volatile("barrier.cluster.wait.aligned;" ::: "memory");
}
__device__ __forceinline__ void mbar_init(uint32_t mb, unsigned cnt) {
  asm volatile("mbarrier.init.shared::cta.b64 [%0], %1;" :: "r"(mb), "r"(cnt) : "memory");
}
__device__ __forceinline__ void mbar_arm(uint32_t mb, unsigned tx) {
  asm volatile("mbarrier.arrive.expect_tx.shared::cta.b64 _, [%0], %1;"
               :: "r"(mb), "r"(tx) : "memory");
}
__device__ __forceinline__ void st_async64(uint32_t ra, ull v, uint32_t rmb) {
  asm volatile("st.async.shared::cluster.mbarrier::complete_tx::bytes.b64 [%0], %1, [%2];"
               :: "r"(ra), "l"(v), "r"(rmb) : "memory");
}
__device__ __forceinline__ void waitp(uint32_t mb, unsigned ph) {
  unsigned done;
  asm volatile(
      "{\n\t.reg .pred p;\n\t"
      "mbarrier.try_wait.parity.acquire.cluster.shared::cta.b64 p, [%1], %2;\n\t"
      "selp.u32 %0,1,0,p;\n\t}"
      : "=r"(done) : "r"(mb), "r"(ph) : "memory");
  while (!done) {
    asm volatile(
        "{\n\t.reg .pred p;\n\t"
        "mbarrier.try_wait.parity.acquire.cluster.shared::cta.b64 p, [%1], %2, 0x989680;\n\t"
        "selp.u32 %0,1,0,p;\n\t}"
        : "=r"(done) : "r"(mb), "r"(ph) : "memory");
  }
}
__device__ __forceinline__ float ftanh(float x) {
  float e = __expf(2.f * x);
  return 1.f - __fdividef(2.f, e + 1.f);
}

// GEMM quarter: thread (cq, kq) computes output cols {cq, cq+64} for 4 samples
// (2 pair groups), k in [kq*32, kq*32+32). src is pair-interleaved [g*256+k*2].
__device__ __forceinline__ void gemm_q(const float (&w)[2][32],
                                       const float* __restrict__ src,
                                       float* __restrict__ dst, int kq, int cq) {
  ull a00 = 0, a01 = 0, a10 = 0, a11 = 0;
  const float* s0 = src + (kq << 6);
#pragma unroll
  for (int i = 0; i < 32; i += 2) {
    ulonglong2 xa = *(const ulonglong2*)(s0 + (i << 1));         // g0, k=i,i+1
    ulonglong2 xb = *(const ulonglong2*)(s0 + 256 + (i << 1));   // g1
    ull w00 = pk(w[0][i]), w01 = pk(w[0][i + 1]);
    ull w10 = pk(w[1][i]), w11 = pk(w[1][i + 1]);
    a00 = f2fma(w00, xa.x, a00); a00 = f2fma(w01, xa.y, a00);
    a01 = f2fma(w00, xb.x, a01); a01 = f2fma(w01, xb.y, a01);
    a10 = f2fma(w10, xa.x, a10); a10 = f2fma(w11, xa.y, a10);
    a11 = f2fma(w10, xb.x, a11); a11 = f2fma(w11, xb.y, a11);
  }
  float* d0 = dst + (kq << 9);
  *(ull*)(d0 + (cq << 1))               = a00;
  *(ull*)(d0 + 256 + (cq << 1))         = a01;
  *(ull*)(d0 + ((cq + 64) << 1))        = a10;
  *(ull*)(d0 + 256 + ((cq + 64) << 1))  = a11;
}

__global__ void __launch_bounds__(256, 1) __cluster_dims__(4, 1, 1)
vino_kernel(const float* __restrict__ x0g, const float* __restrict__ W1g,
            const float* __restrict__ b1g, const float* __restrict__ u1g,
            const float* __restrict__ W2g, const float* __restrict__ b2g,
            const int* __restrict__ nsp, float* __restrict__ out, int B) {
  __shared__ float sm[SMF];
  __shared__ __align__(8) unsigned long long smbar[2];
  const int t = threadIdx.x;
  const int w = t >> 5, lane = t & 31;
  const int cq = t & 63, kq = t >> 6;       // GEMM tiling
  const int c = t & 127, g = t >> 7;        // epilogue tiling (d == c)
  const int e2 = t << 1;                    // pair-slot float offset
  uint32_t rank; asm("mov.u32 %0, %%cluster_ctarank;" : "=r"(rank));
  const int hbase = (int)rank << 7;
  const int sb = (blockIdx.x >> 2) << 2;

  // ---- persistent weight registers (2 cols x 32 k each) ----
  float w1r[2][32], w2r[2][32];
#pragma unroll
  for (int i = 0; i < 32; ++i) {
    const int kk = (kq << 5) + i;
    w1r[0][i] = W1g[kk * 512 + hbase + cq];
    w1r[1][i] = W1g[kk * 512 + hbase + cq + 64];
    w2r[0][i] = W2g[(hbase + kk) * 128 + cq];
    w2r[1][i] = W2g[(hbase + kk) * 128 + cq + 64];
  }

  // ---- per-thread constants: b1, u1, M (h-col c), b2 (d-col c) ----
  const float b1r = b1g[hbase + c];
  const float u1r = u1g[hbase + c];
  const ull b2p = pk(b2g[c]);
  float mr = 0.f;
#pragma unroll 4
  for (int i = 0; i < 128; ++i)
    mr = fmaf(W1g[i * 512 + hbase + c], W2g[(hbase + c) * 128 + i], mr);

  // ---- state init (pair-interleaved) ----
  ull y = mk2(x0g[(sb + 2 * g) * 128 + c], x0g[(sb + 2 * g + 1) * 128 + c]);
  ull xs = y;
  *(ull*)&sm[oXs + e2] = xs;

  // mbarriers: count=1, armed for 4 ranks x 256 thr x 8B = 8192 tx bytes
  const uint32_t mb0 = smem_u32(&smbar[0]);
  if (t == 0) {
    mbar_init(mb0, 1); mbar_init(mb0 + 8, 1);
    mbar_arm(mb0, 8192u); mbar_arm(mb0 + 8, 8192u);
  }

  // ---- log p(x0) ----
  {
    float q0 = lo32(y), q1 = hi32(y);
    float s0 = wsum(q0 * q0), s1 = wsum(q1 * q1);
    if (lane == 0) { sm[oScr + w * 2] = s0; sm[oScr + w * 2 + 1] = s1; }
  }
  __syncthreads();
  if (t < 4) {
    const int gg = t >> 1, sp = t & 1;
    float ss = 0.f;
#pragma unroll
    for (int q = 0; q < 4; ++q) ss += sm[oScr + ((4 * gg + q) << 1) + sp];
    sm[oLp + t] = -0.5f * ss - 117.6241322501981f;  // 64*log(2*pi)
  }
  csync();  // mbarrier arming + smem init visible cluster-wide

  const int ns = *nsp;
  const float dt = 1.0f / (float)ns;
  const uint32_t sbase = smem_u32(sm);
  ull ks0 = 0, ks1 = 0, ks2 = 0, ks3 = 0, ks4 = 0, ks5 = 0;
  ull acc_tr = 0, acc_dot = 0;
  unsigned par0 = 0, par1 = 0;

  for (int step = 0; step < ns; ++step) {
    const float tstep = (float)step * dt;
#pragma unroll 1
    for (int stage = 0; stage < 6; ++stage) {
      const float coef = dt * cBWv[stage];
      const float tcur = tstep + cCC[stage] * dt;
      const int p = stage & 1;

      __syncthreads();                       // S_A: oXs visible
      gemm_q(w1r, sm + oXs, sm + oHP, kq, cq);
      __syncthreads();                       // S_B

      // tanh + per-thread trace accumulation
      {
        ull h = f2add(f2add(*(const ull*)&sm[oHP + e2], *(const ull*)&sm[oHP + 512 + e2]),
                      f2add(*(const ull*)&sm[oHP + 1024 + e2], *(const ull*)&sm[oHP + 1536 + e2]));
        h = f2add(h, pk(fmaf(tcur, u1r, b1r)));
        float a0 = ftanh(lo32(h)), a1 = ftanh(hi32(h));
        *(ull*)&sm[oA + e2] = mk2(a0, a1);
        acc_tr = f2fma(mk2((1.f - a0 * a0) * mr, (1.f - a1 * a1) * mr), pk(coef), acc_tr);
      }
      __syncthreads();                       // S_C
      gemm_q(w2r, sm + oA, sm + oHP, kq, cq);
      __syncthreads();                       // S_D

      // fold 4 k-quarters, push to all 4 ranks (incl. self) via st.async
      {
        ull v = f2add(f2add(*(const ull*)&sm[oHP + e2], *(const ull*)&sm[oHP + 512 + e2]),
                      f2add(*(const ull*)&sm[oHP + 1024 + e2], *(const ull*)&sm[oHP + 1536 + e2]));
        const uint32_t loff = sbase + (uint32_t)(oPb + (p << 11) + ((int)rank << 9) + e2) * 4u;
        const uint32_t lmb = mb0 + (p << 3);
#pragma unroll
        for (uint32_t r = 0; r < 4; ++r)
          st_async64(mapa_u32(loff, r), v, mapa_u32(lmb, r));
      }

      // wait for all 8KB of this buffer, re-arm for its next use
      {
        const uint32_t lmb = mb0 + (p << 3);
        unsigned ph = p ? par1 : par0;
        waitp(lmb, ph);
        if (p) par1 ^= 1; else par0 ^= 1;
        if (t == 0) mbar_arm(lmb, 8192u);
      }

      // assemble dxdt, accumulate dot, advance RK state (registers)
      {
        const float* pb = sm + oPb + (p << 11);
        ull kacc = f2add(f2add(*(const ull*)(pb + e2), *(const ull*)(pb + 512 + e2)),
                         f2add(*(const ull*)(pb + 1024 + e2), *(const ull*)(pb + 1536 + e2)));
        kacc = f2add(kacc, b2p);
        acc_dot = f2fma(f2mul(xs, kacc), pk(coef), acc_dot);
        ull acc;
        switch (stage) {
          case 0:
            ks0 = kacc;
            acc = f2mul(pk(0.2f), ks0);
            xs = f2fma(pk(dt), acc, y);
            break;
          case 1:
            ks1 = kacc;
            acc = f2mul(pk(0.075f), ks0);
            acc = f2fma(pk(0.225f), ks1, acc);
            xs = f2fma(pk(dt), acc, y);
            break;
          case 2:
            ks2 = kacc;
            acc = f2mul(pk((float)(44.0 / 45.0)), ks0);
            acc = f2fma(pk((float)(-56.0 / 15.0)), ks1, acc);
            acc = f2fma(pk((float)(32.0 / 9.0)), ks2, acc);
            xs = f2fma(pk(dt), acc, y);
            break;
          case 3:
            ks3 = kacc;
            acc = f2mul(pk((float)(19372.0 / 6561.0)), ks0);
            acc = f2fma(pk((float)(-25360.0 / 2187.0)), ks1, acc);
            acc = f2fma(pk((float)(64448.0 / 6561.0)), ks2, acc);
            acc = f2fma(pk((float)(-212.0 / 729.0)), ks3, acc);
            xs = f2fma(pk(dt), acc, y);
            break;
          case 4:
            ks4 = kacc;
            acc = f2mul(pk((float)(9017.0 / 3168.0)), ks0);
            acc = f2fma(pk((float)(-355.0 / 33.0)), ks1, acc);
            acc = f2fma(pk((float)(46732.0 / 5247.0)), ks2, acc);
            acc = f2fma(pk((float)(49.0 / 176.0)), ks3, acc);
            acc = f2fma(pk((float)(-5103.0 / 18656.0)), ks4, acc);
            xs = f2fma(pk(dt), acc, y);
            break;
          default:
            ks5 = kacc;
            acc = f2mul(pk((float)(35.0 / 384.0)), ks0);
            acc = f2fma(pk((float)(500.0 / 1113.0)), ks2, acc);
            acc = f2fma(pk((float)(125.0 / 192.0)), ks3, acc);
            acc = f2fma(pk((float)(-2187.0 / 6784.0)), ks4, acc);
            acc = f2fma(pk((float)(11.0 / 84.0)), ks5, acc);
            y = f2fma(pk(dt), acc, y);
            xs = y;
            break;
        }
        *(ull*)&sm[oXs + e2] = xs;
      }
    }
  }

  // ---- outputs: z ----
  out[(sb + 2 * g) * 128 + c]     = lo32(y);
  out[(sb + 2 * g + 1) * 128 + c] = hi32(y);

  // ---- final reductions: trace (cross-CTA) and dot (local) ----
  {
    float tlo = wsum(lo32(acc_tr)), thi = wsum(hi32(acc_tr));
    float dlo = wsum(lo32(acc_dot)), dhi = wsum(hi32(acc_dot));
    if (lane == 0) {
      sm[oScr + w * 4 + 0] = tlo; sm[oScr + w * 4 + 1] = thi;
      sm[oScr + w * 4 + 2] = dlo; sm[oScr + w * 4 + 3] = dhi;
    }
  }
  __syncthreads();
  if (t < 4) {
    const int gg = t >> 1, sp = t & 1;
    float T = 0.f, D = 0.f;
#pragma unroll
    for (int q = 0; q < 4; ++q) {
      T += sm[oScr + (4 * gg + q) * 4 + sp];
      D += sm[oScr + (4 * gg + q) * 4 + 2 + sp];
    }
    sm[oTx + t] = T;
    sm[oScr + t] = D;  // reuse scratch (post-sync)
  }
  csync();
  if (t < 4) {
    const uint32_t ta = smem_u32(&sm[oTx + t]);
    float T4 = 0.f;
#pragma unroll
    for (uint32_t r = 0; r < 4; ++r) T4 += ldcf(ta, r);
    out[B * 128 + sb + t]     = sm[oLp + t] - T4;       // log_px
    out[B * 128 + B + sb + t] = sm[oScr + t] - T4;      // kl
  }
  csync();  // keep smem alive until peers finish remote reads
}

extern "C" void kernel_launch(void* const* d_in, const int* in_sizes, int n_in,
                              void* d_out, int out_size) {
  const float* x0 = (const float*)d_in[0];
  const float* W1 = (const float*)d_in[1];
  const float* b1 = (const float*)d_in[2];
  const float* u1 = (const float*)d_in[3];
  const float* W2 = (const float*)d_in[4];
  const float* b2 = (const float*)d_in[5];
  const int*   ns = (const int*)d_in[6];
  float* out = (float*)d_out;
  int B = in_sizes[0] / 128;
  vino_kernel<<<B, 256>>>(x0, W1, b1, u1, W2, b2, ns, out, B);
}